// round 3
// baseline (speedup 1.0000x reference)
#include <cuda_runtime.h>

// TAHE: masked cosine-similarity weighted pooling.
// out[b,d] = sum_l [ts[b,l]>0] * (cos(cur_n[b], rec[b,l]) + 1)/2 * items[b,l,d]
// B=4096, L=200, D=128, all f32. HBM-bound; ~50% of l-rows masked out -> skip their loads.

#define TB 4096
#define TL 200
#define TD 128
#define WARPS 8
#define TEPS 1e-12f

__global__ __launch_bounds__(WARPS * 32, 1)
void tahe_kernel(const float* __restrict__ rec,
                 const float* __restrict__ cur,
                 const int*   __restrict__ ts,
                 const float* __restrict__ items,
                 float*       __restrict__ out)
{
    const int b    = blockIdx.x;
    const int wid  = threadIdx.x >> 5;
    const int lane = threadIdx.x & 31;

    // ---- normalize cur[b,:] (redundant per warp; 2KB, L1-resident) ----
    const float4* cur4 = reinterpret_cast<const float4*>(cur + (size_t)b * TD);
    float4 c = __ldg(&cur4[lane]);
    float ss = c.x * c.x + c.y * c.y + c.z * c.z + c.w * c.w;
    #pragma unroll
    for (int o = 16; o > 0; o >>= 1)
        ss += __shfl_xor_sync(0xffffffffu, ss, o);
    const float rn = rsqrtf(fmaxf(ss, TEPS));
    c.x *= rn; c.y *= rn; c.z *= rn; c.w *= rn;

    const float4* rec4 = reinterpret_cast<const float4*>(rec   + (size_t)b * TL * TD);
    const float4* it4  = reinterpret_cast<const float4*>(items + (size_t)b * TL * TD);
    const int*    tsb  = ts + (size_t)b * TL;

    float4 acc = make_float4(0.f, 0.f, 0.f, 0.f);

    // ---- mainloop: each warp handles l = wid, wid+8, ... ----
    for (int l = wid; l < TL; l += WARPS) {
        if (__ldg(&tsb[l]) <= 0) continue;   // warp-uniform: skip whole 512B rows

        const float4 r = __ldg(&rec4[l * 32 + lane]);
        const float4 v = __ldg(&it4 [l * 32 + lane]);

        float dot = r.x * c.x + r.y * c.y + r.z * c.z + r.w * c.w;
        float sq  = r.x * r.x + r.y * r.y + r.z * r.z + r.w * r.w;
        #pragma unroll
        for (int o = 16; o > 0; o >>= 1) {
            dot += __shfl_xor_sync(0xffffffffu, dot, o);
            sq  += __shfl_xor_sync(0xffffffffu, sq,  o);
        }

        const float sim = dot * rsqrtf(fmaxf(sq, TEPS));
        const float w   = (sim + 1.0f) * 0.5f;

        acc.x += w * v.x;
        acc.y += w * v.y;
        acc.z += w * v.z;
        acc.w += w * v.w;
    }

    // ---- cross-warp reduction of per-lane float4 partials ----
    __shared__ float4 red[WARPS][32];
    red[wid][lane] = acc;
    __syncthreads();

    if (wid == 0) {
        float4 s = red[0][lane];
        #pragma unroll
        for (int w = 1; w < WARPS; ++w) {
            const float4 t = red[w][lane];
            s.x += t.x; s.y += t.y; s.z += t.z; s.w += t.w;
        }
        reinterpret_cast<float4*>(out + (size_t)b * TD)[lane] = s;
    }
}

extern "C" void kernel_launch(void* const* d_in, const int* in_sizes, int n_in,
                              void* d_out, int out_size)
{
    const float* rec   = (const float*)d_in[0]; // recentTimeRepresentations [B,L,D]
    const float* cur   = (const float*)d_in[1]; // curTimeRepresentation    [B,D]
    const int*   ts    = (const int*)  d_in[2]; // recentTimestamps         [B,L]
    const float* items = (const float*)d_in[3]; // recentItemEmbeddings     [B,L,D]
    float*       out   = (float*)d_out;         // [B,D]

    tahe_kernel<<<TB, WARPS * 32>>>(rec, cur, ts, items, out);
}